// round 14
// baseline (speedup 1.0000x reference)
#include <cuda_runtime.h>
#include <cuda_fp16.h>
#include <cstdint>

// Problem constants
#define L 3
#define B 2
#define C 2048
#define HW 3600          // 60*60
#define CH 256
#define KD (L*C)         // 6144 fused K dimension
#define HWP 3840         // 30*128 = 15*256, padded spatial
#define SP 3616          // 113 * 32, padded support dim for gemm2 K
#define TEMP 20.0f
#define ATT_WT 0.3f

#define BKK 32                  // fp16 k per pipeline stage
#define NCHUNK (KD / BKK)       // 192
#define NCHUNK2 (SP / BKK)      // 113
#define ROWB 80                 // smem row stride bytes (32 fp16 = 64B + 16B pad)
#define STAGES 4

// gemm1 (128x256): per stage A=128*80, B=256*80
#define G1_AT (128 * ROWB)            // 10240
#define G1_BT (256 * ROWB)            // 20480
#define G1_STAGE (G1_AT + G1_BT)      // 30720
#define G1_SMEM (STAGES * G1_STAGE)   // 122880

// gemm2 (128x128) legacy tile
#define TILEB (128 * ROWB)            // 10240
#define G2_SMEM (STAGES * 2 * TILEB)  // 81920

// ---------------- scratch (static __device__ — no allocations) ----------------
__device__ __half g_Aq[(size_t)B * HWP * KD];    // [b][p][k]  w_l * normalized fq
__device__ __half g_As[(size_t)B * HWP * KD];    // [b][p][k]  normalized fs
__device__ float  g_red[(size_t)B * HWP * HWP];  // [b][q][s]  logits (gemm1 out)
__device__ __half g_attnh[(size_t)B * HWP * SP]; // [b][q][s]  fp16 attn (pad rows stay 0)
__device__ __half g_vh[(size_t)B * CH * SP];     // [b][c][s]  fp16 f_s
__device__ float  g_invq[L * B * HW];
__device__ float  g_invs[L * B * HW];

// ======================= PTX helpers ==========================================
__device__ __forceinline__ uint32_t smem_u32(const void* p) {
    uint32_t a;
    asm("{ .reg .u64 t; cvta.to.shared.u64 t, %1; cvt.u32.u64 %0, t; }" : "=r"(a) : "l"(p));
    return a;
}
__device__ __forceinline__ void cpasync16(uint32_t dst, const void* src) {
    asm volatile("cp.async.cg.shared.global [%0], [%1], 16;"
        :: "r"(dst), "l"(__cvta_generic_to_global(src)) : "memory");
}
#define CP_COMMIT()  asm volatile("cp.async.commit_group;" ::: "memory")
#define CP_WAIT(n)   asm volatile("cp.async.wait_group %0;" :: "n"(n) : "memory")

__device__ __forceinline__ void ldsm_x4(uint32_t* r, uint32_t addr) {
    asm volatile("ldmatrix.sync.aligned.m8n8.x4.shared.b16 {%0,%1,%2,%3}, [%4];"
        : "=r"(r[0]), "=r"(r[1]), "=r"(r[2]), "=r"(r[3]) : "r"(addr));
}
__device__ __forceinline__ void ldsm_x2(uint32_t* r, uint32_t addr) {
    asm volatile("ldmatrix.sync.aligned.m8n8.x2.shared.b16 {%0,%1}, [%2];"
        : "=r"(r[0]), "=r"(r[1]) : "r"(addr));
}
__device__ __forceinline__ void mma16816(float* c, const uint32_t* a, const uint32_t* b) {
    asm volatile("mma.sync.aligned.m16n8k16.row.col.f32.f16.f16.f32 "
        "{%0,%1,%2,%3}, {%4,%5,%6,%7}, {%8,%9}, {%0,%1,%2,%3};"
        : "+f"(c[0]), "+f"(c[1]), "+f"(c[2]), "+f"(c[3])
        : "r"(a[0]), "r"(a[1]), "r"(a[2]), "r"(a[3]), "r"(b[0]), "r"(b[1]));
}

// ---------------- 1) inverse norms over C (coalesced over spatial) ------------
__global__ void norm_kernel(const float* __restrict__ x, int which) {
    float* inv = which ? g_invs : g_invq;
    int p = blockIdx.x * blockDim.x + threadIdx.x;
    int lb = blockIdx.y;                    // l*B + b
    if (p >= HW) return;
    const float* base = x + (size_t)lb * C * HW + p;
    float s = 0.f;
    #pragma unroll 8
    for (int c = 0; c < C; c++) {
        float v = base[(size_t)c * HW];
        s += v * v;
    }
    float n = sqrtf(s);
    inv[lb * HW + p] = 1.0f / fmaxf(n, 1e-12f);
}

// ---------------- 2) normalize + fp16 + transpose to [b][p][k] ----------------
// grid: (HWP/32, C/32, L*B), block (32, 8)
__global__ void pack_kernel(const float* __restrict__ x, const float* __restrict__ wts,
                            int which) {
    const float* inv = which ? g_invs : g_invq;
    __half* out = which ? g_As : g_Aq;
    int l = blockIdx.z / B;
    int b = blockIdx.z % B;
    int p0 = blockIdx.x * 32;
    int c0 = blockIdx.y * 32;
    int tx = threadIdx.x, ty = threadIdx.y;
    float w = which ? 1.0f : wts[l];

    __shared__ float tile[32][33];

    int p = p0 + tx;
    float iv = (p < HW) ? inv[(l * B + b) * HW + p] * w : 0.f;
    #pragma unroll
    for (int r = 0; r < 4; r++) {
        int c = c0 + ty + r * 8;
        float v = (p < HW) ? x[((size_t)(l * B + b) * C + c) * HW + p] * iv : 0.f;
        tile[ty + r * 8][tx] = v;
    }
    __syncthreads();

    #pragma unroll
    for (int r = 0; r < 4; r++) {
        int pp = p0 + ty + r * 8;
        int cc = c0 + tx;
        float v = tile[tx][ty + r * 8];
        out[((size_t)b * HWP + pp) * KD + (l * C + cc)] = __float2half(v);
    }
}

// ---------------- 2b) pack f_s to fp16 [b][c][s], zero-padded s ---------------
__global__ void pack_v_kernel(const float* __restrict__ v) {
    int idx = blockIdx.x * blockDim.x + threadIdx.x;
    if (idx >= B * CH * SP) return;
    int s = idx % SP;
    int bc = idx / SP;
    float val = (s < HW) ? v[(size_t)bc * HW + s] : 0.f;
    g_vh[idx] = __float2half(val);
}

// ---------------- 3) gemm1: CTA 128x256, warp tile 64x64 ----------------------
// red[q][s] = sum_k Aq[q][k] * As[s][k]
__global__ void __launch_bounds__(256, 1) gemm1_mma_kernel() {
    extern __shared__ __align__(16) char sm[];
    int tid  = threadIdx.x;
    int wid  = tid >> 5;
    int lane = tid & 31;
    int wm = wid & 1;        // 2 warps -> M
    int wn = wid >> 1;       // 4 warps -> N (64 each)

    int m0 = blockIdx.x * 128;
    int n0 = blockIdx.y * 256;
    int b  = blockIdx.z;

    const __half* Ag = g_Aq + (size_t)b * HWP * KD + (size_t)m0 * KD;
    const __half* Bg = g_As + (size_t)b * HWP * KD + (size_t)n0 * KD;

    uint32_t sbase = smem_u32(sm);

    // loaders: A = 128 rows x 4 chunks (2/thread), B = 256 rows x 4 chunks (4/thread)
    int a_ldrow = tid >> 1;
    int a_ldc2  = (tid & 1) * 2;

    auto load_chunk = [&](int chunk, int buf) {
        const __half* As_ = Ag + chunk * BKK;
        const __half* Bs_ = Bg + chunk * BKK;
        uint32_t a_s = sbase + buf * G1_STAGE;
        uint32_t b_s = a_s + G1_AT;
        uint32_t aro = a_ldrow * ROWB + a_ldc2 * 16;
        cpasync16(a_s + aro,      As_ + (size_t)a_ldrow * KD + a_ldc2 * 8);
        cpasync16(a_s + aro + 16, As_ + (size_t)a_ldrow * KD + a_ldc2 * 8 + 8);
        const __half* brow = Bs_ + (size_t)tid * KD;
        uint32_t bro = tid * ROWB;
        #pragma unroll
        for (int c = 0; c < 4; c++)
            cpasync16(b_s + bro + c * 16, brow + c * 8);
        CP_COMMIT();
    };

    float acc[4][8][4];
    #pragma unroll
    for (int i = 0; i < 4; i++)
        #pragma unroll
        for (int j = 0; j < 8; j++)
            #pragma unroll
            for (int k = 0; k < 4; k++) acc[i][j][k] = 0.f;

    // ldmatrix lane addressing
    int a_row   = lane & 15;
    int a_chunk = (lane >> 4) & 1;
    int b_row   = lane & 7;
    int b_half  = (lane >> 4) & 1;   // 0: n-tile lower 8 rows, 1: upper 8 rows
    int b_chunk = (lane >> 3) & 1;   // k chunk

    #pragma unroll
    for (int s = 0; s < STAGES - 1; s++) load_chunk(s, s);

    for (int i = 0; i < NCHUNK; i++) {
        CP_WAIT(STAGES - 2);
        __syncthreads();
        if (i + STAGES - 1 < NCHUNK) load_chunk(i + STAGES - 1, (i + STAGES - 1) % STAGES);
        else CP_COMMIT();

        int buf = i % STAGES;
        uint32_t a_s = sbase + buf * G1_STAGE;
        uint32_t b_s = a_s + G1_AT;

        #pragma unroll
        for (int ks = 0; ks < 2; ks++) {
            uint32_t afrag[4][4];
            uint32_t bfrag[8][2];
            #pragma unroll
            for (int mi = 0; mi < 4; mi++) {
                uint32_t addr = a_s + (uint32_t)(wm * 64 + mi * 16 + a_row) * ROWB
                              + ks * 32 + a_chunk * 16;
                ldsm_x4(afrag[mi], addr);
            }
            #pragma unroll
            for (int nj = 0; nj < 4; nj++) {
                uint32_t r[4];
                uint32_t addr = b_s + (uint32_t)(wn * 64 + nj * 16 + b_half * 8 + b_row) * ROWB
                              + ks * 32 + b_chunk * 16;
                ldsm_x4(r, addr);
                bfrag[2 * nj][0] = r[0]; bfrag[2 * nj][1] = r[1];
                bfrag[2 * nj + 1][0] = r[2]; bfrag[2 * nj + 1][1] = r[3];
            }
            #pragma unroll
            for (int mi = 0; mi < 4; mi++)
                #pragma unroll
                for (int nj = 0; nj < 8; nj++)
                    mma16816(acc[mi][nj], afrag[mi], bfrag[nj]);
        }
    }

    // epilogue
    int er = lane >> 2;
    int ec = (lane & 3) * 2;
    #pragma unroll
    for (int mi = 0; mi < 4; mi++) {
        int r_base = m0 + wm * 64 + mi * 16 + er;
        #pragma unroll
        for (int nj = 0; nj < 8; nj++) {
            int cidx = n0 + wn * 64 + nj * 8 + ec;
            float2* p0v = (float2*)&g_red[((size_t)b * HWP + r_base) * HWP + cidx];
            *p0v = make_float2(acc[mi][nj][0], acc[mi][nj][1]);
            float2* p1v = (float2*)&g_red[((size_t)b * HWP + r_base + 8) * HWP + cidx];
            *p1v = make_float2(acc[mi][nj][2], acc[mi][nj][3]);
        }
    }
}

// ============ gemm2 mainloop (CTA 128x128, 8 warps 2Mx4N, warp 64x32) =========
__device__ __forceinline__ void mma_mainloop(const __half* Ag, const __half* Bg,
                                             size_t lda, size_t ldb, int nchunk,
                                             char* sm, float acc[4][4][4]) {
    int tid  = threadIdx.x;
    int wid  = tid >> 5;
    int lane = tid & 31;
    int wm = wid & 1;
    int wn = wid >> 1;

    uint32_t sbase = smem_u32(sm);
    int ld_row = tid >> 1;
    int ld_c2  = (tid & 1) * 2;

    auto load_chunk = [&](int chunk, int buf) {
        const __half* As_ = Ag + chunk * BKK;
        const __half* Bs_ = Bg + chunk * BKK;
        uint32_t a_s = sbase + buf * (2 * TILEB);
        uint32_t b_s = a_s + TILEB;
        uint32_t ro = ld_row * ROWB + ld_c2 * 16;
        cpasync16(a_s + ro,      As_ + (size_t)ld_row * lda + ld_c2 * 8);
        cpasync16(a_s + ro + 16, As_ + (size_t)ld_row * lda + ld_c2 * 8 + 8);
        cpasync16(b_s + ro,      Bs_ + (size_t)ld_row * ldb + ld_c2 * 8);
        cpasync16(b_s + ro + 16, Bs_ + (size_t)ld_row * ldb + ld_c2 * 8 + 8);
        CP_COMMIT();
    };

    int a_row   = lane & 15;
    int a_chunk = (lane >> 4) & 1;
    int b_row   = lane & 7;
    int b_chunk = (lane >> 3) & 1;

    #pragma unroll
    for (int s = 0; s < STAGES - 1; s++) load_chunk(s, s);

    for (int i = 0; i < nchunk; i++) {
        CP_WAIT(STAGES - 2);
        __syncthreads();
        if (i + STAGES - 1 < nchunk) load_chunk(i + STAGES - 1, (i + STAGES - 1) % STAGES);
        else CP_COMMIT();

        int buf = i % STAGES;
        uint32_t a_s = sbase + buf * (2 * TILEB);
        uint32_t b_s = a_s + TILEB;

        #pragma unroll
        for (int ks = 0; ks < 2; ks++) {
            uint32_t afrag[4][4];
            uint32_t bfrag[4][2];
            #pragma unroll
            for (int mi = 0; mi < 4; mi++) {
                uint32_t addr = a_s + (uint32_t)(wm * 64 + mi * 16 + a_row) * ROWB
                              + ks * 32 + a_chunk * 16;
                ldsm_x4(afrag[mi], addr);
            }
            #pragma unroll
            for (int ni = 0; ni < 4; ni++) {
                uint32_t addr = b_s + (uint32_t)(wn * 32 + ni * 8 + b_row) * ROWB
                              + ks * 32 + b_chunk * 16;
                ldsm_x2(bfrag[ni], addr);
            }
            #pragma unroll
            for (int mi = 0; mi < 4; mi++)
                #pragma unroll
                for (int ni = 0; ni < 4; ni++)
                    mma16816(acc[mi][ni], afrag[mi], bfrag[ni]);
        }
    }
}

// ---------------- 4) row softmax over s -> fp16 attn (zero-padded) ------------
__global__ __launch_bounds__(256) void softmax_kernel() {
    __shared__ float row[HW];
    __shared__ float sred[256];
    int b = blockIdx.x / HW;
    int q = blockIdx.x % HW;
    size_t base = ((size_t)b * HWP + q) * HWP;
    int tid = threadIdx.x;

    float mx = -1e30f;
    for (int s = tid; s < HW; s += 256) {
        float v = g_red[base + s] * TEMP;
        row[s] = v;
        mx = fmaxf(mx, v);
    }
    sred[tid] = mx;
    __syncthreads();
    for (int st = 128; st > 0; st >>= 1) {
        if (tid < st) sred[tid] = fmaxf(sred[tid], sred[tid + st]);
        __syncthreads();
    }
    mx = sred[0];
    __syncthreads();

    float sm = 0.f;
    for (int s = tid; s < HW; s += 256) {
        float e = __expf(row[s] - mx);
        row[s] = e;
        sm += e;
    }
    sred[tid] = sm;
    __syncthreads();
    for (int st = 128; st > 0; st >>= 1) {
        if (tid < st) sred[tid] += sred[tid + st];
        __syncthreads();
    }
    float invs = 1.0f / sred[0];

    __half* out = g_attnh + ((size_t)b * HWP + q) * SP;
    for (int s = tid; s < SP; s += 256)
        out[s] = __float2half((s < HW) ? row[s] * invs : 0.f);
}

// ---------------- 5) gemm2 (HMMA): att_fq[c][q] = sum_s attn[q][s]*v[c][s] ----
__global__ void __launch_bounds__(256) gemm2_mma_kernel(const float* __restrict__ fqin,
                                                        float* __restrict__ outfq,
                                                        float* __restrict__ outatt) {
    extern __shared__ __align__(16) char sm[];
    int m0 = blockIdx.x * 128;   // c
    int n0 = blockIdx.y * 128;   // q
    int b  = blockIdx.z;

    float acc[4][4][4];
    #pragma unroll
    for (int i = 0; i < 4; i++)
        #pragma unroll
        for (int j = 0; j < 4; j++)
            #pragma unroll
            for (int k = 0; k < 4; k++) acc[i][j][k] = 0.f;

    mma_mainloop(g_vh    + ((size_t)b * CH  + m0) * SP,
                 g_attnh + ((size_t)b * HWP + n0) * SP,
                 SP, SP, NCHUNK2, sm, acc);

    int tid  = threadIdx.x;
    int wid  = tid >> 5;
    int lane = tid & 31;
    int wm = wid & 1, wn = wid >> 1;
    int er = lane >> 2;
    int ec = (lane & 3) * 2;
    const float inv13 = 1.0f / (1.0f + ATT_WT);

    #pragma unroll
    for (int mi = 0; mi < 4; mi++) {
        int c0 = m0 + wm * 64 + mi * 16 + er;
        #pragma unroll
        for (int ni = 0; ni < 4; ni++) {
            int q0 = n0 + wn * 32 + ni * 8 + ec;
            if (q0 < HW) {
                size_t o0 = ((size_t)b * CH + c0) * HW + q0;
                float a0 = acc[mi][ni][0], a1 = acc[mi][ni][1];
                ((float2*)&outatt[o0])[0] = make_float2(a0, a1);
                float2 fq = *(const float2*)&fqin[o0];
                ((float2*)&outfq[o0])[0] =
                    make_float2((fq.x + a0 * ATT_WT) * inv13, (fq.y + a1 * ATT_WT) * inv13);

                size_t o1 = ((size_t)b * CH + c0 + 8) * HW + q0;
                float a2 = acc[mi][ni][2], a3 = acc[mi][ni][3];
                ((float2*)&outatt[o1])[0] = make_float2(a2, a3);
                float2 fq1 = *(const float2*)&fqin[o1];
                ((float2*)&outfq[o1])[0] =
                    make_float2((fq1.x + a2 * ATT_WT) * inv13, (fq1.y + a3 * ATT_WT) * inv13);
            }
        }
    }
}

// ---------------- launch ------------------------------------------------------
extern "C" void kernel_launch(void* const* d_in, const int* in_sizes, int n_in,
                              void* d_out, int out_size) {
    const float* fq_feats = (const float*)d_in[0];
    const float* fs_feats = (const float*)d_in[1];
    const float* f_q      = (const float*)d_in[2];
    const float* f_s      = (const float*)d_in[3];
    const float* w        = (const float*)d_in[4];

    float* outfq  = (float*)d_out;
    float* outatt = outfq + (size_t)B * CH * HW;

    static int smem_set = 0;
    if (!smem_set) {
        cudaFuncSetAttribute(gemm1_mma_kernel, cudaFuncAttributeMaxDynamicSharedMemorySize, G1_SMEM);
        cudaFuncSetAttribute(gemm2_mma_kernel, cudaFuncAttributeMaxDynamicSharedMemorySize, G2_SMEM);
        smem_set = 1;
    }

    // 1) inverse norms
    dim3 gN((HW + 255) / 256, L * B);
    norm_kernel<<<gN, 256>>>(fq_feats, 0);
    norm_kernel<<<gN, 256>>>(fs_feats, 1);

    // 2) normalize + fp16 + transpose; pack v
    dim3 gP(HWP / 32, C / 32, L * B);
    dim3 bP(32, 8);
    pack_kernel<<<gP, bP>>>(fq_feats, w, 0);
    pack_kernel<<<gP, bP>>>(fs_feats, w, 1);
    pack_v_kernel<<<(B * CH * SP + 255) / 256, 256>>>(f_s);

    // 3) HMMA gemm1: red = Aq @ As^T  (M=N=3840, K=6144, per batch)
    dim3 g1(HWP / 128, HWP / 256, B);
    gemm1_mma_kernel<<<g1, 256, G1_SMEM>>>();

    // 4) softmax -> fp16 attn
    softmax_kernel<<<B * HW, 256>>>();

    // 5) HMMA gemm2 + fused epilogue
    dim3 g2(CH / 128, HWP / 128, B);
    gemm2_mma_kernel<<<g2, 256, G2_SMEM>>>(f_q, outfq, outatt);
}

// round 15
// speedup vs baseline: 1.1294x; 1.1294x over previous
#include <cuda_runtime.h>
#include <cuda_fp16.h>
#include <cstdint>

// Problem constants
#define L 3
#define B 2
#define C 2048
#define HW 3600          // 60*60
#define CH 256
#define KD (L*C)         // 6144 fused K dimension
#define HWP 3712         // 29 * 128, padded spatial (gemm1 M/N, gemm2 N)
#define SP 3616          // 113 * 32, padded support dim for gemm2 K
#define TEMP 20.0f
#define ATT_WT 0.3f

#define BKK 32                  // fp16 k per pipeline stage
#define NCHUNK (KD / BKK)       // 192
#define NCHUNK2 (SP / BKK)      // 113
#define ROWB 80                 // smem row stride bytes (32 fp16 = 64B + 16B pad)
#define TILEB (128 * ROWB)      // 10240 bytes per operand tile
#define STAGES 4
#define SMEM_SZ (STAGES * 2 * TILEB)   // 81920 -> 2 CTAs/SM

// ---------------- scratch (static __device__ — no allocations) ----------------
__device__ __half g_Aq[(size_t)B * HWP * KD];    // [b][p][k]  w_l * normalized fq
__device__ __half g_As[(size_t)B * HWP * KD];    // [b][p][k]  normalized fs
__device__ float  g_red[(size_t)B * HWP * HWP];  // [b][q][s]  logits (gemm1 out)
__device__ __half g_attnh[(size_t)B * HWP * SP]; // [b][q][s]  fp16 attn (pad rows stay 0)
__device__ __half g_vh[(size_t)B * CH * SP];     // [b][c][s]  fp16 f_s
__device__ float  g_invq[L * B * HW];
__device__ float  g_invs[L * B * HW];

// ======================= PTX helpers ==========================================
__device__ __forceinline__ uint32_t smem_u32(const void* p) {
    uint32_t a;
    asm("{ .reg .u64 t; cvta.to.shared.u64 t, %1; cvt.u32.u64 %0, t; }" : "=r"(a) : "l"(p));
    return a;
}
__device__ __forceinline__ void cpasync16(uint32_t dst, const void* src) {
    asm volatile("cp.async.cg.shared.global [%0], [%1], 16;"
        :: "r"(dst), "l"(__cvta_generic_to_global(src)) : "memory");
}
#define CP_COMMIT()  asm volatile("cp.async.commit_group;" ::: "memory")
#define CP_WAIT(n)   asm volatile("cp.async.wait_group %0;" :: "n"(n) : "memory")

__device__ __forceinline__ void ldsm_x4(uint32_t* r, uint32_t addr) {
    asm volatile("ldmatrix.sync.aligned.m8n8.x4.shared.b16 {%0,%1,%2,%3}, [%4];"
        : "=r"(r[0]), "=r"(r[1]), "=r"(r[2]), "=r"(r[3]) : "r"(addr));
}
__device__ __forceinline__ void ldsm_x2(uint32_t* r, uint32_t addr) {
    asm volatile("ldmatrix.sync.aligned.m8n8.x2.shared.b16 {%0,%1}, [%2];"
        : "=r"(r[0]), "=r"(r[1]) : "r"(addr));
}
__device__ __forceinline__ void mma16816(float* c, const uint32_t* a, const uint32_t* b) {
    asm volatile("mma.sync.aligned.m16n8k16.row.col.f32.f16.f16.f32 "
        "{%0,%1,%2,%3}, {%4,%5,%6,%7}, {%8,%9}, {%0,%1,%2,%3};"
        : "+f"(c[0]), "+f"(c[1]), "+f"(c[2]), "+f"(c[3])
        : "r"(a[0]), "r"(a[1]), "r"(a[2]), "r"(a[3]), "r"(b[0]), "r"(b[1]));
}

// ---------------- 1) inverse norms over C (coalesced over spatial) ------------
__global__ void norm_kernel(const float* __restrict__ x, int which) {
    float* inv = which ? g_invs : g_invq;
    int p = blockIdx.x * blockDim.x + threadIdx.x;
    int lb = blockIdx.y;                    // l*B + b
    if (p >= HW) return;
    const float* base = x + (size_t)lb * C * HW + p;
    float s = 0.f;
    #pragma unroll 8
    for (int c = 0; c < C; c++) {
        float v = base[(size_t)c * HW];
        s += v * v;
    }
    float n = sqrtf(s);
    inv[lb * HW + p] = 1.0f / fmaxf(n, 1e-12f);
}

// ---------------- 2) normalize + fp16 + transpose to [b][p][k] ----------------
// grid: (HWP/32, C/32, L*B), block (32, 8)
__global__ void pack_kernel(const float* __restrict__ x, const float* __restrict__ wts,
                            int which) {
    const float* inv = which ? g_invs : g_invq;
    __half* out = which ? g_As : g_Aq;
    int l = blockIdx.z / B;
    int b = blockIdx.z % B;
    int p0 = blockIdx.x * 32;
    int c0 = blockIdx.y * 32;
    int tx = threadIdx.x, ty = threadIdx.y;
    float w = which ? 1.0f : wts[l];

    __shared__ float tile[32][33];

    int p = p0 + tx;
    float iv = (p < HW) ? inv[(l * B + b) * HW + p] * w : 0.f;
    #pragma unroll
    for (int r = 0; r < 4; r++) {
        int c = c0 + ty + r * 8;
        float v = (p < HW) ? x[((size_t)(l * B + b) * C + c) * HW + p] * iv : 0.f;
        tile[ty + r * 8][tx] = v;
    }
    __syncthreads();

    #pragma unroll
    for (int r = 0; r < 4; r++) {
        int pp = p0 + ty + r * 8;
        int cc = c0 + tx;
        float v = tile[tx][ty + r * 8];
        out[((size_t)b * HWP + pp) * KD + (l * C + cc)] = __float2half(v);
    }
}

// ---------------- 2b) pack f_s to fp16 [b][c][s], zero-padded s ---------------
__global__ void pack_v_kernel(const float* __restrict__ v) {
    int idx = blockIdx.x * blockDim.x + threadIdx.x;
    if (idx >= B * CH * SP) return;
    int s = idx % SP;
    int bc = idx / SP;
    float val = (s < HW) ? v[(size_t)bc * HW + s] : 0.f;
    g_vh[idx] = __float2half(val);
}

// ============ shared HMMA mainloop (CTA 128x128, 8 warps 2Mx4N) ================
__device__ __forceinline__ void mma_mainloop(const __half* Ag, const __half* Bg,
                                             size_t lda, size_t ldb, int nchunk,
                                             char* sm, float acc[4][4][4]) {
    int tid  = threadIdx.x;
    int wid  = tid >> 5;
    int lane = tid & 31;
    int wm = wid & 1;
    int wn = wid >> 1;

    uint32_t sbase = smem_u32(sm);
    int ld_row = tid >> 1;
    int ld_c2  = (tid & 1) * 2;

    auto load_chunk = [&](int chunk, int buf) {
        const __half* As_ = Ag + chunk * BKK;
        const __half* Bs_ = Bg + chunk * BKK;
        uint32_t a_s = sbase + buf * (2 * TILEB);
        uint32_t b_s = a_s + TILEB;
        uint32_t ro = ld_row * ROWB + ld_c2 * 16;
        cpasync16(a_s + ro,      As_ + (size_t)ld_row * lda + ld_c2 * 8);
        cpasync16(a_s + ro + 16, As_ + (size_t)ld_row * lda + ld_c2 * 8 + 8);
        cpasync16(b_s + ro,      Bs_ + (size_t)ld_row * ldb + ld_c2 * 8);
        cpasync16(b_s + ro + 16, Bs_ + (size_t)ld_row * ldb + ld_c2 * 8 + 8);
        CP_COMMIT();
    };

    int a_row   = lane & 15;
    int a_chunk = (lane >> 4) & 1;
    int b_row   = lane & 7;
    int b_chunk = (lane >> 3) & 1;

    #pragma unroll
    for (int s = 0; s < STAGES - 1; s++) load_chunk(s, s);

    for (int i = 0; i < nchunk; i++) {
        CP_WAIT(STAGES - 2);
        __syncthreads();
        if (i + STAGES - 1 < nchunk) load_chunk(i + STAGES - 1, (i + STAGES - 1) % STAGES);
        else CP_COMMIT();

        int buf = i % STAGES;
        uint32_t a_s = sbase + buf * (2 * TILEB);
        uint32_t b_s = a_s + TILEB;

        #pragma unroll
        for (int ks = 0; ks < 2; ks++) {
            uint32_t afrag[4][4];
            uint32_t bfrag[4][2];
            #pragma unroll
            for (int mi = 0; mi < 4; mi++) {
                uint32_t addr = a_s + (uint32_t)(wm * 64 + mi * 16 + a_row) * ROWB
                              + ks * 32 + a_chunk * 16;
                ldsm_x4(afrag[mi], addr);
            }
            #pragma unroll
            for (int ni = 0; ni < 4; ni++) {
                uint32_t addr = b_s + (uint32_t)(wn * 32 + ni * 8 + b_row) * ROWB
                              + ks * 32 + b_chunk * 16;
                ldsm_x2(bfrag[ni], addr);
            }
            #pragma unroll
            for (int mi = 0; mi < 4; mi++)
                #pragma unroll
                for (int ni = 0; ni < 4; ni++)
                    mma16816(acc[mi][ni], afrag[mi], bfrag[ni]);
        }
    }
}

// ---------------- 3) gemm1: red[q][s] = sum_k Aq[q][k]*As[s][k] ---------------
__global__ void __launch_bounds__(256, 2) gemm1_mma_kernel() {
    extern __shared__ __align__(16) char sm[];
    int m0 = blockIdx.x * 128;
    int n0 = blockIdx.y * 128;
    int b  = blockIdx.z;

    float acc[4][4][4];
    #pragma unroll
    for (int i = 0; i < 4; i++)
        #pragma unroll
        for (int j = 0; j < 4; j++)
            #pragma unroll
            for (int k = 0; k < 4; k++) acc[i][j][k] = 0.f;

    mma_mainloop(g_Aq + (size_t)b * HWP * KD + (size_t)m0 * KD,
                 g_As + (size_t)b * HWP * KD + (size_t)n0 * KD,
                 KD, KD, NCHUNK, sm, acc);

    int tid  = threadIdx.x;
    int wid  = tid >> 5;
    int lane = tid & 31;
    int wm = wid & 1, wn = wid >> 1;
    int er = lane >> 2;
    int ec = (lane & 3) * 2;
    #pragma unroll
    for (int mi = 0; mi < 4; mi++) {
        int r_base = m0 + wm * 64 + mi * 16 + er;
        #pragma unroll
        for (int ni = 0; ni < 4; ni++) {
            int cidx = n0 + wn * 32 + ni * 8 + ec;
            float2* p0v = (float2*)&g_red[((size_t)b * HWP + r_base) * HWP + cidx];
            *p0v = make_float2(acc[mi][ni][0], acc[mi][ni][1]);
            float2* p1v = (float2*)&g_red[((size_t)b * HWP + r_base + 8) * HWP + cidx];
            *p1v = make_float2(acc[mi][ni][2], acc[mi][ni][3]);
        }
    }
}

// ---------------- 4) row softmax over s -> fp16 attn (zero-padded) ------------
__global__ __launch_bounds__(256) void softmax_kernel() {
    __shared__ float row[HW];
    __shared__ float sred[256];
    int b = blockIdx.x / HW;
    int q = blockIdx.x % HW;
    size_t base = ((size_t)b * HWP + q) * HWP;
    int tid = threadIdx.x;

    float mx = -1e30f;
    for (int s = tid; s < HW; s += 256) {
        float v = g_red[base + s] * TEMP;
        row[s] = v;
        mx = fmaxf(mx, v);
    }
    sred[tid] = mx;
    __syncthreads();
    for (int st = 128; st > 0; st >>= 1) {
        if (tid < st) sred[tid] = fmaxf(sred[tid], sred[tid + st]);
        __syncthreads();
    }
    mx = sred[0];
    __syncthreads();

    float sm = 0.f;
    for (int s = tid; s < HW; s += 256) {
        float e = __expf(row[s] - mx);
        row[s] = e;
        sm += e;
    }
    sred[tid] = sm;
    __syncthreads();
    for (int st = 128; st > 0; st >>= 1) {
        if (tid < st) sred[tid] += sred[tid + st];
        __syncthreads();
    }
    float invs = 1.0f / sred[0];

    __half* out = g_attnh + ((size_t)b * HWP + q) * SP;
    for (int s = tid; s < SP; s += 256)
        out[s] = __float2half((s < HW) ? row[s] * invs : 0.f);
}

// ---------------- 5) gemm2 (HMMA): att_fq[c][q] = sum_s attn[q][s]*v[c][s] ----
__global__ void __launch_bounds__(256, 2) gemm2_mma_kernel(const float* __restrict__ fqin,
                                                           float* __restrict__ outfq,
                                                           float* __restrict__ outatt) {
    extern __shared__ __align__(16) char sm[];
    int m0 = blockIdx.x * 128;   // c
    int n0 = blockIdx.y * 128;   // q
    int b  = blockIdx.z;

    float acc[4][4][4];
    #pragma unroll
    for (int i = 0; i < 4; i++)
        #pragma unroll
        for (int j = 0; j < 4; j++)
            #pragma unroll
            for (int k = 0; k < 4; k++) acc[i][j][k] = 0.f;

    mma_mainloop(g_vh    + ((size_t)b * CH  + m0) * SP,
                 g_attnh + ((size_t)b * HWP + n0) * SP,
                 SP, SP, NCHUNK2, sm, acc);

    int tid  = threadIdx.x;
    int wid  = tid >> 5;
    int lane = tid & 31;
    int wm = wid & 1, wn = wid >> 1;
    int er = lane >> 2;
    int ec = (lane & 3) * 2;
    const float inv13 = 1.0f / (1.0f + ATT_WT);

    #pragma unroll
    for (int mi = 0; mi < 4; mi++) {
        int c0 = m0 + wm * 64 + mi * 16 + er;
        #pragma unroll
        for (int ni = 0; ni < 4; ni++) {
            int q0 = n0 + wn * 32 + ni * 8 + ec;
            if (q0 < HW) {
                size_t o0 = ((size_t)b * CH + c0) * HW + q0;
                float a0 = acc[mi][ni][0], a1 = acc[mi][ni][1];
                ((float2*)&outatt[o0])[0] = make_float2(a0, a1);
                float2 fq = *(const float2*)&fqin[o0];
                ((float2*)&outfq[o0])[0] =
                    make_float2((fq.x + a0 * ATT_WT) * inv13, (fq.y + a1 * ATT_WT) * inv13);

                size_t o1 = ((size_t)b * CH + c0 + 8) * HW + q0;
                float a2 = acc[mi][ni][2], a3 = acc[mi][ni][3];
                ((float2*)&outatt[o1])[0] = make_float2(a2, a3);
                float2 fq1 = *(const float2*)&fqin[o1];
                ((float2*)&outfq[o1])[0] =
                    make_float2((fq1.x + a2 * ATT_WT) * inv13, (fq1.y + a3 * ATT_WT) * inv13);
            }
        }
    }
}

// ---------------- launch ------------------------------------------------------
extern "C" void kernel_launch(void* const* d_in, const int* in_sizes, int n_in,
                              void* d_out, int out_size) {
    const float* fq_feats = (const float*)d_in[0];
    const float* fs_feats = (const float*)d_in[1];
    const float* f_q      = (const float*)d_in[2];
    const float* f_s      = (const float*)d_in[3];
    const float* w        = (const float*)d_in[4];

    float* outfq  = (float*)d_out;
    float* outatt = outfq + (size_t)B * CH * HW;

    static int smem_set = 0;
    if (!smem_set) {
        cudaFuncSetAttribute(gemm1_mma_kernel, cudaFuncAttributeMaxDynamicSharedMemorySize, SMEM_SZ);
        cudaFuncSetAttribute(gemm2_mma_kernel, cudaFuncAttributeMaxDynamicSharedMemorySize, SMEM_SZ);
        smem_set = 1;
    }

    // 1) inverse norms
    dim3 gN((HW + 255) / 256, L * B);
    norm_kernel<<<gN, 256>>>(fq_feats, 0);
    norm_kernel<<<gN, 256>>>(fs_feats, 1);

    // 2) normalize + fp16 + transpose; pack v
    dim3 gP(HWP / 32, C / 32, L * B);
    dim3 bP(32, 8);
    pack_kernel<<<gP, bP>>>(fq_feats, w, 0);
    pack_kernel<<<gP, bP>>>(fs_feats, w, 1);
    pack_v_kernel<<<(B * CH * SP + 255) / 256, 256>>>(f_s);

    // 3) HMMA gemm1: red = Aq @ As^T  (M=N=3712, K=6144, per batch)
    dim3 g1(HWP / 128, HWP / 128, B);
    gemm1_mma_kernel<<<g1, 256, SMEM_SZ>>>();

    // 4) softmax -> fp16 attn
    softmax_kernel<<<B * HW, 256>>>();

    // 5) HMMA gemm2 + fused epilogue
    dim3 g2(CH / 128, HWP / 128, B);
    gemm2_mma_kernel<<<g2, 256, SMEM_SZ>>>(f_q, outfq, outatt);
}

// round 16
// speedup vs baseline: 1.2240x; 1.0838x over previous
#include <cuda_runtime.h>
#include <cuda_fp16.h>
#include <cstdint>

// Problem constants
#define L 3
#define B 2
#define C 2048
#define HW 3600          // 60*60
#define CH 256
#define KD (L*C)         // 6144 fused K dimension
#define HWP 3712         // 29 * 128, padded spatial (gemm1 M/N, gemm2 N)
#define SP 3648          // 57 * 64, padded support dim for gemm2 K
#define TEMP 20.0f
#define ATT_WT 0.3f

#define BKK 64                  // fp16 k per pipeline stage
#define NCHUNK (KD / BKK)       // 96
#define NCHUNK2 (SP / BKK)      // 57
#define ROWB 128                // smem row stride bytes (64 fp16, SW128 swizzle, no pad)
#define TILEB (128 * ROWB)      // 16384 bytes per operand tile
#define STAGES 3
#define SMEM_SZ (STAGES * 2 * TILEB)   // 98304 -> 2 CTAs/SM

// ---------------- scratch (static __device__ — no allocations) ----------------
__device__ __half g_Aq[(size_t)B * HWP * KD];    // [b][p][k]  w_l * normalized fq
__device__ __half g_As[(size_t)B * HWP * KD];    // [b][p][k]  normalized fs
__device__ float  g_red[(size_t)B * HWP * HWP];  // [b][q][s]  logits (gemm1 out)
__device__ __half g_attnh[(size_t)B * HWP * SP]; // [b][q][s]  fp16 attn (pad rows stay 0)
__device__ __half g_vh[(size_t)B * CH * SP];     // [b][c][s]  fp16 f_s
__device__ float  g_invq[L * B * HW];
__device__ float  g_invs[L * B * HW];

// ======================= PTX helpers ==========================================
__device__ __forceinline__ uint32_t smem_u32(const void* p) {
    uint32_t a;
    asm("{ .reg .u64 t; cvta.to.shared.u64 t, %1; cvt.u32.u64 %0, t; }" : "=r"(a) : "l"(p));
    return a;
}
__device__ __forceinline__ void cpasync16(uint32_t dst, const void* src) {
    asm volatile("cp.async.cg.shared.global [%0], [%1], 16;"
        :: "r"(dst), "l"(__cvta_generic_to_global(src)) : "memory");
}
#define CP_COMMIT()  asm volatile("cp.async.commit_group;" ::: "memory")
#define CP_WAIT(n)   asm volatile("cp.async.wait_group %0;" :: "n"(n) : "memory")

__device__ __forceinline__ void ldsm_x4(uint32_t* r, uint32_t addr) {
    asm volatile("ldmatrix.sync.aligned.m8n8.x4.shared.b16 {%0,%1,%2,%3}, [%4];"
        : "=r"(r[0]), "=r"(r[1]), "=r"(r[2]), "=r"(r[3]) : "r"(addr));
}
__device__ __forceinline__ void mma16816(float* c, const uint32_t* a, const uint32_t* b) {
    asm volatile("mma.sync.aligned.m16n8k16.row.col.f32.f16.f16.f32 "
        "{%0,%1,%2,%3}, {%4,%5,%6,%7}, {%8,%9}, {%0,%1,%2,%3};"
        : "+f"(c[0]), "+f"(c[1]), "+f"(c[2]), "+f"(c[3])
        : "r"(a[0]), "r"(a[1]), "r"(a[2]), "r"(a[3]), "r"(b[0]), "r"(b[1]));
}

// ---------------- 1) inverse norms over C (coalesced over spatial) ------------
__global__ void norm_kernel(const float* __restrict__ x, int which) {
    float* inv = which ? g_invs : g_invq;
    int p = blockIdx.x * blockDim.x + threadIdx.x;
    int lb = blockIdx.y;                    // l*B + b
    if (p >= HW) return;
    const float* base = x + (size_t)lb * C * HW + p;
    float s = 0.f;
    #pragma unroll 8
    for (int c = 0; c < C; c++) {
        float v = base[(size_t)c * HW];
        s += v * v;
    }
    float n = sqrtf(s);
    inv[lb * HW + p] = 1.0f / fmaxf(n, 1e-12f);
}

// ---------------- 2) normalize + fp16 + transpose to [b][p][k] ----------------
// grid: (HWP/32, C/32, L*B), block (32, 8)
__global__ void pack_kernel(const float* __restrict__ x, const float* __restrict__ wts,
                            int which) {
    const float* inv = which ? g_invs : g_invq;
    __half* out = which ? g_As : g_Aq;
    int l = blockIdx.z / B;
    int b = blockIdx.z % B;
    int p0 = blockIdx.x * 32;
    int c0 = blockIdx.y * 32;
    int tx = threadIdx.x, ty = threadIdx.y;
    float w = which ? 1.0f : wts[l];

    __shared__ float tile[32][33];

    int p = p0 + tx;
    float iv = (p < HW) ? inv[(l * B + b) * HW + p] * w : 0.f;
    #pragma unroll
    for (int r = 0; r < 4; r++) {
        int c = c0 + ty + r * 8;
        float v = (p < HW) ? x[((size_t)(l * B + b) * C + c) * HW + p] * iv : 0.f;
        tile[ty + r * 8][tx] = v;
    }
    __syncthreads();

    #pragma unroll
    for (int r = 0; r < 4; r++) {
        int pp = p0 + ty + r * 8;
        int cc = c0 + tx;
        float v = tile[tx][ty + r * 8];
        out[((size_t)b * HWP + pp) * KD + (l * C + cc)] = __float2half(v);
    }
}

// ---------------- 2b) pack f_s to fp16 [b][c][s], zero-padded s ---------------
__global__ void pack_v_kernel(const float* __restrict__ v) {
    int idx = blockIdx.x * blockDim.x + threadIdx.x;
    if (idx >= B * CH * SP) return;
    int s = idx % SP;
    int bc = idx / SP;
    float val = (s < HW) ? v[(size_t)bc * HW + s] : 0.f;
    g_vh[idx] = __float2half(val);
}

// ============ shared HMMA mainloop (CTA 128x128, 8 warps 2Mx4N) ================
// SW128-swizzled smem: row = 128 bytes (64 fp16), seg16 position = seg ^ (row&7).
__device__ __forceinline__ void mma_mainloop(const __half* Ag, const __half* Bg,
                                             size_t lda, size_t ldb, int nchunk,
                                             char* sm, float acc[4][4][4]) {
    int tid  = threadIdx.x;
    int wid  = tid >> 5;
    int lane = tid & 31;
    int wm = wid & 1;
    int wn = wid >> 1;

    uint32_t sbase = smem_u32(sm);

    // loader: 128 rows x 128B per operand; 2 threads/row, 4x16B segs each
    int ld_row  = tid >> 1;
    int ld_seg0 = (tid & 1) * 4;
    uint32_t ld_swz_base = (uint32_t)ld_row * ROWB;
    int ld_rmod = ld_row & 7;

    auto load_chunk = [&](int chunk, int buf) {
        const __half* As_ = Ag + (size_t)chunk * BKK;
        const __half* Bs_ = Bg + (size_t)chunk * BKK;
        uint32_t a_s = sbase + buf * (2 * TILEB);
        uint32_t b_s = a_s + TILEB;
        const __half* arow = As_ + (size_t)ld_row * lda;
        const __half* brow = Bs_ + (size_t)ld_row * ldb;
        #pragma unroll
        for (int c = 0; c < 4; c++) {
            int seg = ld_seg0 + c;
            uint32_t soff = ld_swz_base + (uint32_t)((seg ^ ld_rmod) * 16);
            cpasync16(a_s + soff, arow + seg * 8);
            cpasync16(b_s + soff, brow + seg * 8);
        }
        CP_COMMIT();
    };

    // ldmatrix lane addressing
    int a_row   = lane & 15;          // row within 16-row A subtile
    int a_chunk = (lane >> 4) & 1;    // 16B k-half
    int b_g     = lane >> 3;          // 0..3 group for B x4
    int b_row_in = (((b_g >> 1) & 1) * 8) + (lane & 7);  // row within 16-row B pair
    int b_chunk = b_g & 1;

    #pragma unroll
    for (int s = 0; s < STAGES - 1; s++) load_chunk(s, s);

    for (int i = 0; i < nchunk; i++) {
        CP_WAIT(STAGES - 2);
        __syncthreads();
        if (i + STAGES - 1 < nchunk) load_chunk(i + STAGES - 1, (i + STAGES - 1) % STAGES);
        else CP_COMMIT();

        int buf = i % STAGES;
        uint32_t a_s = sbase + buf * (2 * TILEB);
        uint32_t b_s = a_s + TILEB;

        #pragma unroll
        for (int ks = 0; ks < 4; ks++) {
            uint32_t afrag[4][4];
            uint32_t bfrag[4][2];
            #pragma unroll
            for (int mi = 0; mi < 4; mi++) {
                int row = wm * 64 + mi * 16 + a_row;
                int seg = (ks * 2 + a_chunk) ^ (row & 7);
                ldsm_x4(afrag[mi], a_s + (uint32_t)row * ROWB + (uint32_t)(seg * 16));
            }
            #pragma unroll
            for (int nj = 0; nj < 2; nj++) {
                uint32_t r[4];
                int row = wn * 32 + nj * 16 + b_row_in;
                int seg = (ks * 2 + b_chunk) ^ (row & 7);
                ldsm_x4(r, b_s + (uint32_t)row * ROWB + (uint32_t)(seg * 16));
                bfrag[2 * nj][0]     = r[0]; bfrag[2 * nj][1]     = r[1];
                bfrag[2 * nj + 1][0] = r[2]; bfrag[2 * nj + 1][1] = r[3];
            }
            #pragma unroll
            for (int mi = 0; mi < 4; mi++)
                #pragma unroll
                for (int ni = 0; ni < 4; ni++)
                    mma16816(acc[mi][ni], afrag[mi], bfrag[ni]);
        }
    }
}

// ---------------- 3) gemm1: red[q][s] = sum_k Aq[q][k]*As[s][k] ---------------
__global__ void __launch_bounds__(256, 2) gemm1_mma_kernel() {
    extern __shared__ __align__(16) char sm[];
    int m0 = blockIdx.x * 128;
    int n0 = blockIdx.y * 128;
    int b  = blockIdx.z;

    float acc[4][4][4];
    #pragma unroll
    for (int i = 0; i < 4; i++)
        #pragma unroll
        for (int j = 0; j < 4; j++)
            #pragma unroll
            for (int k = 0; k < 4; k++) acc[i][j][k] = 0.f;

    mma_mainloop(g_Aq + (size_t)b * HWP * KD + (size_t)m0 * KD,
                 g_As + (size_t)b * HWP * KD + (size_t)n0 * KD,
                 KD, KD, NCHUNK, sm, acc);

    int tid  = threadIdx.x;
    int wid  = tid >> 5;
    int lane = tid & 31;
    int wm = wid & 1, wn = wid >> 1;
    int er = lane >> 2;
    int ec = (lane & 3) * 2;
    #pragma unroll
    for (int mi = 0; mi < 4; mi++) {
        int r_base = m0 + wm * 64 + mi * 16 + er;
        #pragma unroll
        for (int ni = 0; ni < 4; ni++) {
            int cidx = n0 + wn * 32 + ni * 8 + ec;
            float2* p0v = (float2*)&g_red[((size_t)b * HWP + r_base) * HWP + cidx];
            *p0v = make_float2(acc[mi][ni][0], acc[mi][ni][1]);
            float2* p1v = (float2*)&g_red[((size_t)b * HWP + r_base + 8) * HWP + cidx];
            *p1v = make_float2(acc[mi][ni][2], acc[mi][ni][3]);
        }
    }
}

// ---------------- 4) row softmax over s -> fp16 attn (zero-padded) ------------
__global__ __launch_bounds__(256) void softmax_kernel() {
    __shared__ float row[HW];
    __shared__ float sred[256];
    int b = blockIdx.x / HW;
    int q = blockIdx.x % HW;
    size_t base = ((size_t)b * HWP + q) * HWP;
    int tid = threadIdx.x;

    float mx = -1e30f;
    for (int s = tid; s < HW; s += 256) {
        float v = g_red[base + s] * TEMP;
        row[s] = v;
        mx = fmaxf(mx, v);
    }
    sred[tid] = mx;
    __syncthreads();
    for (int st = 128; st > 0; st >>= 1) {
        if (tid < st) sred[tid] = fmaxf(sred[tid], sred[tid + st]);
        __syncthreads();
    }
    mx = sred[0];
    __syncthreads();

    float sm = 0.f;
    for (int s = tid; s < HW; s += 256) {
        float e = __expf(row[s] - mx);
        row[s] = e;
        sm += e;
    }
    sred[tid] = sm;
    __syncthreads();
    for (int st = 128; st > 0; st >>= 1) {
        if (tid < st) sred[tid] += sred[tid + st];
        __syncthreads();
    }
    float invs = 1.0f / sred[0];

    __half* out = g_attnh + ((size_t)b * HWP + q) * SP;
    for (int s = tid; s < SP; s += 256)
        out[s] = __float2half((s < HW) ? row[s] * invs : 0.f);
}

// ---------------- 5) gemm2 (HMMA): att_fq[c][q] = sum_s attn[q][s]*v[c][s] ----
__global__ void __launch_bounds__(256, 2) gemm2_mma_kernel(const float* __restrict__ fqin,
                                                           float* __restrict__ outfq,
                                                           float* __restrict__ outatt) {
    extern __shared__ __align__(16) char sm[];
    int m0 = blockIdx.x * 128;   // c
    int n0 = blockIdx.y * 128;   // q
    int b  = blockIdx.z;

    float acc[4][4][4];
    #pragma unroll
    for (int i = 0; i < 4; i++)
        #pragma unroll
        for (int j = 0; j < 4; j++)
            #pragma unroll
            for (int k = 0; k < 4; k++) acc[i][j][k] = 0.f;

    mma_mainloop(g_vh    + ((size_t)b * CH  + m0) * SP,
                 g_attnh + ((size_t)b * HWP + n0) * SP,
                 SP, SP, NCHUNK2, sm, acc);

    int tid  = threadIdx.x;
    int wid  = tid >> 5;
    int lane = tid & 31;
    int wm = wid & 1, wn = wid >> 1;
    int er = lane >> 2;
    int ec = (lane & 3) * 2;
    const float inv13 = 1.0f / (1.0f + ATT_WT);

    #pragma unroll
    for (int mi = 0; mi < 4; mi++) {
        int c0 = m0 + wm * 64 + mi * 16 + er;
        #pragma unroll
        for (int ni = 0; ni < 4; ni++) {
            int q0 = n0 + wn * 32 + ni * 8 + ec;
            if (q0 < HW) {
                size_t o0 = ((size_t)b * CH + c0) * HW + q0;
                float a0 = acc[mi][ni][0], a1 = acc[mi][ni][1];
                ((float2*)&outatt[o0])[0] = make_float2(a0, a1);
                float2 fq = *(const float2*)&fqin[o0];
                ((float2*)&outfq[o0])[0] =
                    make_float2((fq.x + a0 * ATT_WT) * inv13, (fq.y + a1 * ATT_WT) * inv13);

                size_t o1 = ((size_t)b * CH + c0 + 8) * HW + q0;
                float a2 = acc[mi][ni][2], a3 = acc[mi][ni][3];
                ((float2*)&outatt[o1])[0] = make_float2(a2, a3);
                float2 fq1 = *(const float2*)&fqin[o1];
                ((float2*)&outfq[o1])[0] =
                    make_float2((fq1.x + a2 * ATT_WT) * inv13, (fq1.y + a3 * ATT_WT) * inv13);
            }
        }
    }
}

// ---------------- launch ------------------------------------------------------
extern "C" void kernel_launch(void* const* d_in, const int* in_sizes, int n_in,
                              void* d_out, int out_size) {
    const float* fq_feats = (const float*)d_in[0];
    const float* fs_feats = (const float*)d_in[1];
    const float* f_q      = (const float*)d_in[2];
    const float* f_s      = (const float*)d_in[3];
    const float* w        = (const float*)d_in[4];

    float* outfq  = (float*)d_out;
    float* outatt = outfq + (size_t)B * CH * HW;

    static int smem_set = 0;
    if (!smem_set) {
        cudaFuncSetAttribute(gemm1_mma_kernel, cudaFuncAttributeMaxDynamicSharedMemorySize, SMEM_SZ);
        cudaFuncSetAttribute(gemm2_mma_kernel, cudaFuncAttributeMaxDynamicSharedMemorySize, SMEM_SZ);
        smem_set = 1;
    }

    // 1) inverse norms
    dim3 gN((HW + 255) / 256, L * B);
    norm_kernel<<<gN, 256>>>(fq_feats, 0);
    norm_kernel<<<gN, 256>>>(fs_feats, 1);

    // 2) normalize + fp16 + transpose; pack v
    dim3 gP(HWP / 32, C / 32, L * B);
    dim3 bP(32, 8);
    pack_kernel<<<gP, bP>>>(fq_feats, w, 0);
    pack_kernel<<<gP, bP>>>(fs_feats, w, 1);
    pack_v_kernel<<<(B * CH * SP + 255) / 256, 256>>>(f_s);

    // 3) HMMA gemm1: red = Aq @ As^T  (M=N=3712, K=6144, per batch)
    dim3 g1(HWP / 128, HWP / 128, B);
    gemm1_mma_kernel<<<g1, 256, SMEM_SZ>>>();

    // 4) softmax -> fp16 attn
    softmax_kernel<<<B * HW, 256>>>();

    // 5) HMMA gemm2 + fused epilogue
    dim3 g2(CH / 128, HWP / 128, B);
    gemm2_mma_kernel<<<g2, 256, SMEM_SZ>>>(f_q, outfq, outatt);
}

// round 17
// speedup vs baseline: 1.2327x; 1.0071x over previous
#include <cuda_runtime.h>
#include <cuda_fp16.h>
#include <cstdint>

// Problem constants
#define L 3
#define B 2
#define C 2048
#define HW 3600          // 60*60
#define CH 256
#define KD (L*C)         // 6144 fused K dimension
#define HWP 3712         // 29 * 128, padded spatial (gemm1 M/N, gemm2 N)
#define SP 3648          // 57 * 64, padded support dim for gemm2 K
#define TEMP 20.0f
#define ATT_WT 0.3f

#define BKK 64                  // fp16 k per pipeline stage
#define NCHUNK (KD / BKK)       // 96
#define NCHUNK2 (SP / BKK)      // 57
#define ROWB 128                // smem row stride bytes (64 fp16, SW128 swizzle, no pad)
#define TILEB (128 * ROWB)      // 16384 bytes per operand tile
#define STAGES 3
#define SMEM_SZ (STAGES * 2 * TILEB)   // 98304 -> 2 CTAs/SM

// ---------------- scratch (static __device__ — no allocations) ----------------
__device__ __half g_Aq[(size_t)B * HWP * KD];    // [b][p][k]  w_l * normalized fq
__device__ __half g_As[(size_t)B * HWP * KD];    // [b][p][k]  normalized fs
__device__ float  g_red[(size_t)B * HWP * HWP];  // [b][q][s]  logits (gemm1 out)
__device__ __half g_attnh[(size_t)B * HWP * SP]; // [b][q][s]  fp16 attn (pad rows stay 0)
__device__ __half g_vh[(size_t)B * CH * SP];     // [b][c][s]  fp16 f_s
__device__ float  g_invq[L * B * HW];
__device__ float  g_invs[L * B * HW];

// ======================= PTX helpers ==========================================
__device__ __forceinline__ uint32_t smem_u32(const void* p) {
    uint32_t a;
    asm("{ .reg .u64 t; cvta.to.shared.u64 t, %1; cvt.u32.u64 %0, t; }" : "=r"(a) : "l"(p));
    return a;
}
__device__ __forceinline__ void cpasync16(uint32_t dst, const void* src) {
    asm volatile("cp.async.cg.shared.global [%0], [%1], 16;"
        :: "r"(dst), "l"(__cvta_generic_to_global(src)) : "memory");
}
#define CP_COMMIT()  asm volatile("cp.async.commit_group;" ::: "memory")
#define CP_WAIT(n)   asm volatile("cp.async.wait_group %0;" :: "n"(n) : "memory")

__device__ __forceinline__ void ldsm_x4(uint32_t* r, uint32_t addr) {
    asm volatile("ldmatrix.sync.aligned.m8n8.x4.shared.b16 {%0,%1,%2,%3}, [%4];"
        : "=r"(r[0]), "=r"(r[1]), "=r"(r[2]), "=r"(r[3]) : "r"(addr));
}
__device__ __forceinline__ void mma16816(float* c, const uint32_t* a, const uint32_t* b) {
    asm volatile("mma.sync.aligned.m16n8k16.row.col.f32.f16.f16.f32 "
        "{%0,%1,%2,%3}, {%4,%5,%6,%7}, {%8,%9}, {%0,%1,%2,%3};"
        : "+f"(c[0]), "+f"(c[1]), "+f"(c[2]), "+f"(c[3])
        : "r"(a[0]), "r"(a[1]), "r"(a[2]), "r"(a[3]), "r"(b[0]), "r"(b[1]));
}

// ---------------- 1) inverse norms over C (coalesced over spatial) ------------
__global__ void norm_kernel(const float* __restrict__ x, int which) {
    float* inv = which ? g_invs : g_invq;
    int p = blockIdx.x * blockDim.x + threadIdx.x;
    int lb = blockIdx.y;                    // l*B + b
    if (p >= HW) return;
    const float* base = x + (size_t)lb * C * HW + p;
    float s = 0.f;
    #pragma unroll 8
    for (int c = 0; c < C; c++) {
        float v = base[(size_t)c * HW];
        s += v * v;
    }
    float n = sqrtf(s);
    inv[lb * HW + p] = 1.0f / fmaxf(n, 1e-12f);
}

// ---------------- 2) normalize + fp16 + transpose to [b][p][k] ----------------
// grid: (HWP/32, C/32, L*B), block (32, 8)
__global__ void pack_kernel(const float* __restrict__ x, const float* __restrict__ wts,
                            int which) {
    const float* inv = which ? g_invs : g_invq;
    __half* out = which ? g_As : g_Aq;
    int l = blockIdx.z / B;
    int b = blockIdx.z % B;
    int p0 = blockIdx.x * 32;
    int c0 = blockIdx.y * 32;
    int tx = threadIdx.x, ty = threadIdx.y;
    float w = which ? 1.0f : wts[l];

    __shared__ float tile[32][33];

    int p = p0 + tx;
    float iv = (p < HW) ? inv[(l * B + b) * HW + p] * w : 0.f;
    #pragma unroll
    for (int r = 0; r < 4; r++) {
        int c = c0 + ty + r * 8;
        float v = (p < HW) ? x[((size_t)(l * B + b) * C + c) * HW + p] * iv : 0.f;
        tile[ty + r * 8][tx] = v;
    }
    __syncthreads();

    #pragma unroll
    for (int r = 0; r < 4; r++) {
        int pp = p0 + ty + r * 8;
        int cc = c0 + tx;
        float v = tile[tx][ty + r * 8];
        out[((size_t)b * HWP + pp) * KD + (l * C + cc)] = __float2half(v);
    }
}

// ---------------- 2b) pack f_s to fp16 [b][c][s], zero-padded s ---------------
__global__ void pack_v_kernel(const float* __restrict__ v) {
    int idx = blockIdx.x * blockDim.x + threadIdx.x;
    if (idx >= B * CH * SP) return;
    int s = idx % SP;
    int bc = idx / SP;
    float val = (s < HW) ? v[(size_t)bc * HW + s] : 0.f;
    g_vh[idx] = __float2half(val);
}

// ============ shared HMMA mainloop (CTA 128x128, 8 warps 2Mx4N) ================
// SW128-swizzled smem: row = 128 bytes (64 fp16), seg16 position = seg ^ (row&7).
__device__ __forceinline__ void mma_mainloop(const __half* Ag, const __half* Bg,
                                             size_t lda, size_t ldb, int nchunk,
                                             char* sm, float acc[4][4][4]) {
    int tid  = threadIdx.x;
    int wid  = tid >> 5;
    int lane = tid & 31;
    int wm = wid & 1;
    int wn = wid >> 1;

    uint32_t sbase = smem_u32(sm);

    // loader: 128 rows x 128B per operand; 2 threads/row, 4x16B segs each
    int ld_row  = tid >> 1;
    int ld_seg0 = (tid & 1) * 4;
    uint32_t ld_swz_base = (uint32_t)ld_row * ROWB;
    int ld_rmod = ld_row & 7;

    auto load_chunk = [&](int chunk, int buf) {
        const __half* As_ = Ag + (size_t)chunk * BKK;
        const __half* Bs_ = Bg + (size_t)chunk * BKK;
        uint32_t a_s = sbase + buf * (2 * TILEB);
        uint32_t b_s = a_s + TILEB;
        const __half* arow = As_ + (size_t)ld_row * lda;
        const __half* brow = Bs_ + (size_t)ld_row * ldb;
        #pragma unroll
        for (int c = 0; c < 4; c++) {
            int seg = ld_seg0 + c;
            uint32_t soff = ld_swz_base + (uint32_t)((seg ^ ld_rmod) * 16);
            cpasync16(a_s + soff, arow + seg * 8);
            cpasync16(b_s + soff, brow + seg * 8);
        }
        CP_COMMIT();
    };

    // ldmatrix lane addressing
    int a_row   = lane & 15;          // row within 16-row A subtile
    int a_chunk = (lane >> 4) & 1;    // 16B k-half
    int b_g     = lane >> 3;          // 0..3 group for B x4
    int b_row_in = (((b_g >> 1) & 1) * 8) + (lane & 7);  // row within 16-row B pair
    int b_chunk = b_g & 1;

    #pragma unroll
    for (int s = 0; s < STAGES - 1; s++) load_chunk(s, s);

    for (int i = 0; i < nchunk; i++) {
        CP_WAIT(STAGES - 2);
        __syncthreads();
        if (i + STAGES - 1 < nchunk) load_chunk(i + STAGES - 1, (i + STAGES - 1) % STAGES);
        else CP_COMMIT();

        int buf = i % STAGES;
        uint32_t a_s = sbase + buf * (2 * TILEB);
        uint32_t b_s = a_s + TILEB;

        #pragma unroll
        for (int ks = 0; ks < 4; ks++) {
            uint32_t afrag[4][4];
            uint32_t bfrag[4][2];
            #pragma unroll
            for (int mi = 0; mi < 4; mi++) {
                int row = wm * 64 + mi * 16 + a_row;
                int seg = (ks * 2 + a_chunk) ^ (row & 7);
                ldsm_x4(afrag[mi], a_s + (uint32_t)row * ROWB + (uint32_t)(seg * 16));
            }
            #pragma unroll
            for (int nj = 0; nj < 2; nj++) {
                uint32_t r[4];
                int row = wn * 32 + nj * 16 + b_row_in;
                int seg = (ks * 2 + b_chunk) ^ (row & 7);
                ldsm_x4(r, b_s + (uint32_t)row * ROWB + (uint32_t)(seg * 16));
                bfrag[2 * nj][0]     = r[0]; bfrag[2 * nj][1]     = r[1];
                bfrag[2 * nj + 1][0] = r[2]; bfrag[2 * nj + 1][1] = r[3];
            }
            #pragma unroll
            for (int mi = 0; mi < 4; mi++)
                #pragma unroll
                for (int ni = 0; ni < 4; ni++)
                    mma16816(acc[mi][ni], afrag[mi], bfrag[ni]);
        }
    }
}

// ---------------- 3) gemm1: red[q][s] = sum_k Aq[q][k]*As[s][k] ---------------
__global__ void __launch_bounds__(256, 2) gemm1_mma_kernel() {
    extern __shared__ __align__(16) char sm[];
    int m0 = blockIdx.x * 128;
    int n0 = blockIdx.y * 128;
    int b  = blockIdx.z;

    float acc[4][4][4];
    #pragma unroll
    for (int i = 0; i < 4; i++)
        #pragma unroll
        for (int j = 0; j < 4; j++)
            #pragma unroll
            for (int k = 0; k < 4; k++) acc[i][j][k] = 0.f;

    mma_mainloop(g_Aq + (size_t)b * HWP * KD + (size_t)m0 * KD,
                 g_As + (size_t)b * HWP * KD + (size_t)n0 * KD,
                 KD, KD, NCHUNK, sm, acc);

    int tid  = threadIdx.x;
    int wid  = tid >> 5;
    int lane = tid & 31;
    int wm = wid & 1, wn = wid >> 1;
    int er = lane >> 2;
    int ec = (lane & 3) * 2;
    #pragma unroll
    for (int mi = 0; mi < 4; mi++) {
        int r_base = m0 + wm * 64 + mi * 16 + er;
        #pragma unroll
        for (int ni = 0; ni < 4; ni++) {
            int cidx = n0 + wn * 32 + ni * 8 + ec;
            float2* p0v = (float2*)&g_red[((size_t)b * HWP + r_base) * HWP + cidx];
            *p0v = make_float2(acc[mi][ni][0], acc[mi][ni][1]);
            float2* p1v = (float2*)&g_red[((size_t)b * HWP + r_base + 8) * HWP + cidx];
            *p1v = make_float2(acc[mi][ni][2], acc[mi][ni][3]);
        }
    }
}

// ---------------- 4) row softmax over s -> fp16 attn (zero-padded) ------------
__global__ __launch_bounds__(256) void softmax_kernel() {
    __shared__ float row[HW];
    __shared__ float sred[256];
    int b = blockIdx.x / HW;
    int q = blockIdx.x % HW;
    size_t base = ((size_t)b * HWP + q) * HWP;
    int tid = threadIdx.x;

    float mx = -1e30f;
    for (int s = tid; s < HW; s += 256) {
        float v = g_red[base + s] * TEMP;
        row[s] = v;
        mx = fmaxf(mx, v);
    }
    sred[tid] = mx;
    __syncthreads();
    for (int st = 128; st > 0; st >>= 1) {
        if (tid < st) sred[tid] = fmaxf(sred[tid], sred[tid + st]);
        __syncthreads();
    }
    mx = sred[0];
    __syncthreads();

    float sm = 0.f;
    for (int s = tid; s < HW; s += 256) {
        float e = __expf(row[s] - mx);
        row[s] = e;
        sm += e;
    }
    sred[tid] = sm;
    __syncthreads();
    for (int st = 128; st > 0; st >>= 1) {
        if (tid < st) sred[tid] += sred[tid + st];
        __syncthreads();
    }
    float invs = 1.0f / sred[0];

    __half* out = g_attnh + ((size_t)b * HWP + q) * SP;
    for (int s = tid; s < SP; s += 256)
        out[s] = __float2half((s < HW) ? row[s] * invs : 0.f);
}

// ---------------- 5) gemm2 (HMMA): att_fq[c][q] = sum_s attn[q][s]*v[c][s] ----
__global__ void __launch_bounds__(256, 2) gemm2_mma_kernel(const float* __restrict__ fqin,
                                                           float* __restrict__ outfq,
                                                           float* __restrict__ outatt) {
    extern __shared__ __align__(16) char sm[];
    int m0 = blockIdx.x * 128;   // c
    int n0 = blockIdx.y * 128;   // q
    int b  = blockIdx.z;

    float acc[4][4][4];
    #pragma unroll
    for (int i = 0; i < 4; i++)
        #pragma unroll
        for (int j = 0; j < 4; j++)
            #pragma unroll
            for (int k = 0; k < 4; k++) acc[i][j][k] = 0.f;

    mma_mainloop(g_vh    + ((size_t)b * CH  + m0) * SP,
                 g_attnh + ((size_t)b * HWP + n0) * SP,
                 SP, SP, NCHUNK2, sm, acc);

    int tid  = threadIdx.x;
    int wid  = tid >> 5;
    int lane = tid & 31;
    int wm = wid & 1, wn = wid >> 1;
    int er = lane >> 2;
    int ec = (lane & 3) * 2;
    const float inv13 = 1.0f / (1.0f + ATT_WT);

    #pragma unroll
    for (int mi = 0; mi < 4; mi++) {
        int c0 = m0 + wm * 64 + mi * 16 + er;
        #pragma unroll
        for (int ni = 0; ni < 4; ni++) {
            int q0 = n0 + wn * 32 + ni * 8 + ec;
            if (q0 < HW) {
                size_t o0 = ((size_t)b * CH + c0) * HW + q0;
                float a0 = acc[mi][ni][0], a1 = acc[mi][ni][1];
                ((float2*)&outatt[o0])[0] = make_float2(a0, a1);
                float2 fq = *(const float2*)&fqin[o0];
                ((float2*)&outfq[o0])[0] =
                    make_float2((fq.x + a0 * ATT_WT) * inv13, (fq.y + a1 * ATT_WT) * inv13);

                size_t o1 = ((size_t)b * CH + c0 + 8) * HW + q0;
                float a2 = acc[mi][ni][2], a3 = acc[mi][ni][3];
                ((float2*)&outatt[o1])[0] = make_float2(a2, a3);
                float2 fq1 = *(const float2*)&fqin[o1];
                ((float2*)&outfq[o1])[0] =
                    make_float2((fq1.x + a2 * ATT_WT) * inv13, (fq1.y + a3 * ATT_WT) * inv13);
            }
        }
    }
}

// ---------------- launch ------------------------------------------------------
extern "C" void kernel_launch(void* const* d_in, const int* in_sizes, int n_in,
                              void* d_out, int out_size) {
    const float* fq_feats = (const float*)d_in[0];
    const float* fs_feats = (const float*)d_in[1];
    const float* f_q      = (const float*)d_in[2];
    const float* f_s      = (const float*)d_in[3];
    const float* w        = (const float*)d_in[4];

    float* outfq  = (float*)d_out;
    float* outatt = outfq + (size_t)B * CH * HW;

    static int smem_set = 0;
    if (!smem_set) {
        cudaFuncSetAttribute(gemm1_mma_kernel, cudaFuncAttributeMaxDynamicSharedMemorySize, SMEM_SZ);
        cudaFuncSetAttribute(gemm2_mma_kernel, cudaFuncAttributeMaxDynamicSharedMemorySize, SMEM_SZ);
        smem_set = 1;
    }

    // 1) inverse norms
    dim3 gN((HW + 255) / 256, L * B);
    norm_kernel<<<gN, 256>>>(fq_feats, 0);
    norm_kernel<<<gN, 256>>>(fs_feats, 1);

    // 2) normalize + fp16 + transpose; pack v
    dim3 gP(HWP / 32, C / 32, L * B);
    dim3 bP(32, 8);
    pack_kernel<<<gP, bP>>>(fq_feats, w, 0);
    pack_kernel<<<gP, bP>>>(fs_feats, w, 1);
    pack_v_kernel<<<(B * CH * SP + 255) / 256, 256>>>(f_s);

    // 3) HMMA gemm1: red = Aq @ As^T  (M=N=3712, K=6144, per batch)
    dim3 g1(HWP / 128, HWP / 128, B);
    gemm1_mma_kernel<<<g1, 256, SMEM_SZ>>>();

    // 4) softmax -> fp16 attn
    softmax_kernel<<<B * HW, 256>>>();

    // 5) HMMA gemm2 + fused epilogue
    dim3 g2(CH / 128, HWP / 128, B);
    gemm2_mma_kernel<<<g2, 256, SMEM_SZ>>>(f_q, outfq, outatt);
}